// round 1
// baseline (speedup 1.0000x reference)
#include <cuda_runtime.h>
#include <math.h>
#include <stdint.h>

// Problem constants
#define GG 32          // B*S graphs
#define NA 64          // atoms per graph
#define HH 300         // hidden
#define AF 133         // atom feature dim
#define BF 147         // bond feature dim
#define AR (GG*NA)     // 2048 atom rows
#define BR (GG*NA*NA)  // 131072 bond rows

// Scratch (static device globals: allocation-free per harness rules)
__device__ float g_input_atom[AR*HH];
__device__ float g_msg_atom[AR*HH];
__device__ float g_agg[AR*HH];
__device__ float g_input_bond[BR*HH];   // 157 MB
__device__ float g_mbA[BR*HH];          // 157 MB
__device__ float g_mbB[BR*HH];          // 157 MB (fallback if d_out lacks space)
__device__ float g_sm[BR];              // softmax(resonance)

// ---------------------------------------------------------------------------
// GEMM 1: input_atom = relu(f_atoms @ W_i_atom); also copies to msg_atom.
// A: [2048, 133], W: [133, 300]. Tiles 64x64, BK=16.
// ---------------------------------------------------------------------------
__global__ void k_input_atom(const float* __restrict__ A, const float* __restrict__ W) {
    const int row0 = blockIdx.y * 64;
    const int col0 = blockIdx.x * 64;
    __shared__ float As[16][68];
    __shared__ float Bs[16][68];
    const int tid = threadIdx.x;
    const int tx = tid & 15, ty = tid >> 4;
    float acc[4][4] = {};
    for (int k0 = 0; k0 < AF; k0 += 16) {
        __syncthreads();
        {
            int kk = tid & 15;
            int k  = k0 + kk;
            #pragma unroll
            for (int q = 0; q < 4; q++) {
                int r = (tid >> 4) + q * 16;
                As[kk][r] = (k < AF) ? A[(row0 + r) * AF + k] : 0.f;
            }
        }
        {
            int nn = tid & 63;
            int c  = col0 + nn;
            #pragma unroll
            for (int q = 0; q < 4; q++) {
                int kk = (tid >> 6) + q * 4;
                int k  = k0 + kk;
                Bs[kk][nn] = (k < AF && c < HH) ? W[k * HH + c] : 0.f;
            }
        }
        __syncthreads();
        #pragma unroll
        for (int kk = 0; kk < 16; kk++) {
            float4 a4 = *(const float4*)&As[kk][ty * 4];
            float4 b4 = *(const float4*)&Bs[kk][tx * 4];
            float a[4] = {a4.x, a4.y, a4.z, a4.w};
            float b[4] = {b4.x, b4.y, b4.z, b4.w};
            #pragma unroll
            for (int i = 0; i < 4; i++)
                #pragma unroll
                for (int j = 0; j < 4; j++)
                    acc[i][j] += a[i] * b[j];
        }
    }
    #pragma unroll
    for (int i = 0; i < 4; i++) {
        int r = row0 + ty * 4 + i;
        #pragma unroll
        for (int j = 0; j < 4; j++) {
            int c = col0 + tx * 4 + j;
            if (c < HH) {
                float v = acc[i][j];
                v = v > 0.f ? v : 0.f;
                g_input_atom[r * HH + c] = v;
                g_msg_atom[r * HH + c]   = v;
            }
        }
    }
}

// ---------------------------------------------------------------------------
// GEMM 2: input_bond = relu((adj * f_bonds) @ W_i_bond)
// A: [131072, 147] scaled per-row by adj; W: [147, 300].
// ---------------------------------------------------------------------------
__global__ void k_input_bond(const float* __restrict__ A, const float* __restrict__ adj,
                             const float* __restrict__ W) {
    const int row0 = blockIdx.y * 64;
    const int col0 = blockIdx.x * 64;
    __shared__ float As[16][68];
    __shared__ float Bs[16][68];
    __shared__ float adjs[64];
    const int tid = threadIdx.x;
    const int tx = tid & 15, ty = tid >> 4;
    if (tid < 64) adjs[tid] = adj[row0 + tid];
    float acc[4][4] = {};
    for (int k0 = 0; k0 < BF; k0 += 16) {
        __syncthreads();
        {
            int kk = tid & 15;
            int k  = k0 + kk;
            #pragma unroll
            for (int q = 0; q < 4; q++) {
                int r = (tid >> 4) + q * 16;
                As[kk][r] = (k < BF) ? A[(row0 + r) * BF + k] * adjs[r] : 0.f;
            }
        }
        {
            int nn = tid & 63;
            int c  = col0 + nn;
            #pragma unroll
            for (int q = 0; q < 4; q++) {
                int kk = (tid >> 6) + q * 4;
                int k  = k0 + kk;
                Bs[kk][nn] = (k < BF && c < HH) ? W[k * HH + c] : 0.f;
            }
        }
        __syncthreads();
        #pragma unroll
        for (int kk = 0; kk < 16; kk++) {
            float4 a4 = *(const float4*)&As[kk][ty * 4];
            float4 b4 = *(const float4*)&Bs[kk][tx * 4];
            float a[4] = {a4.x, a4.y, a4.z, a4.w};
            float b[4] = {b4.x, b4.y, b4.z, b4.w};
            #pragma unroll
            for (int i = 0; i < 4; i++)
                #pragma unroll
                for (int j = 0; j < 4; j++)
                    acc[i][j] += a[i] * b[j];
        }
    }
    #pragma unroll
    for (int i = 0; i < 4; i++) {
        int r = row0 + ty * 4 + i;
        #pragma unroll
        for (int j = 0; j < 4; j++) {
            int c = col0 + tx * 4 + j;
            if (c < HH) {
                float v = acc[i][j];
                g_input_bond[r * HH + c] = v > 0.f ? v : 0.f;
            }
        }
    }
}

// ---------------------------------------------------------------------------
// agg[g,m,h] = sum_n mb[g,n,m,h] * sigmoid(max_n mb[g,n,m,h])
// update=1: msg_atom += agg ; update=0: g_agg = agg
// grid: 2048 blocks (g,m), 320 threads (h)
// ---------------------------------------------------------------------------
__global__ void k_agg(const float* __restrict__ mb, int update) {
    int gm = blockIdx.x;             // (g,m)
    int h = threadIdx.x;
    if (h >= HH) return;
    int g = gm >> 6, m = gm & 63;
    const float* base = mb + ((g * 64) * 64 + m) * HH + h;   // row (g*64+n)*64+m
    float s = 0.f, mx = -INFINITY;
    #pragma unroll 4
    for (int n = 0; n < 64; n++) {
        float v = base[n * 64 * HH];
        s += v;
        mx = fmaxf(mx, v);
    }
    float a = s * (1.f / (1.f + expf(-mx)));
    int idx = gm * HH + h;
    if (update) g_msg_atom[idx] += a;
    else        g_agg[idx] = a;
}

// ---------------------------------------------------------------------------
// resonance + softmax over axis n (first N):
// res[g,n,m] = dot(msg_atom[g,n], msg_atom[g,m]) * adj[g,n,m]
// g_sm[g,n,m] = softmax_n(res[g,:,m])
// grid: 2048 blocks (g, m), 64 threads (n)
// ---------------------------------------------------------------------------
__global__ void k_resonance(const float* __restrict__ adj) {
    int gj = blockIdx.x;
    int g = gj >> 6, m = gj & 63;
    __shared__ float vj[HH];
    __shared__ float rr[64];
    __shared__ float es[64];
    int t = threadIdx.x;             // = n
    for (int k = t; k < HH; k += 64)
        vj[k] = g_msg_atom[(g * 64 + m) * HH + k];
    __syncthreads();
    const float* mi = &g_msg_atom[(g * 64 + t) * HH];
    float s = 0.f;
    #pragma unroll 4
    for (int k = 0; k < HH; k++) s += mi[k] * vj[k];
    s *= adj[(g * 64 + t) * 64 + m];
    rr[t] = s;
    __syncthreads();
    float mx = -INFINITY;
    #pragma unroll
    for (int n = 0; n < 64; n++) mx = fmaxf(mx, rr[n]);
    float e = expf(rr[t] - mx);
    es[t] = e;
    __syncthreads();
    float sum = 0.f;
    #pragma unroll
    for (int n = 0; n < 64; n++) sum += es[n];
    g_sm[(g * 64 + t) * 64 + m] = e / sum;
}

// ---------------------------------------------------------------------------
// Bond update GEMM (dominant):
// out[g,i,j,:] = relu(input_bond[g,i,j,:] +
//                     (adj[g,j,i]*msg_atom[g,i,:] - prev[g,j,i,:]) @ W) * sm[g,i,j]
// One 64-row tile == fixed (g,i), j = 0..63. grid (5 col tiles, 2048 (g,i)).
// ---------------------------------------------------------------------------
__global__ void k_bond_update(const float* __restrict__ adj, const float* __restrict__ W,
                              const float* __restrict__ prev, float* __restrict__ out) {
    const int bm = blockIdx.y;           // (g,i)
    const int g = bm >> 6, i = bm & 63;
    const int col0 = blockIdx.x * 64;
    __shared__ float As[16][68];
    __shared__ float Bs[16][68];
    __shared__ float adjT[64];           // adj[g,j,i]
    __shared__ float smv[64];            // sm[g,i,j]
    const int tid = threadIdx.x;
    const int tx = tid & 15, ty = tid >> 4;
    if (tid < 64) {
        adjT[tid] = adj[(g * 64 + tid) * 64 + i];
        smv[tid]  = g_sm[(g * 64 + i) * 64 + tid];
    }
    const float* ma = &g_msg_atom[(g * 64 + i) * HH];
    float acc[4][4] = {};
    for (int k0 = 0; k0 < HH; k0 += 16) {
        __syncthreads();
        {
            int kk = tid & 15;
            int k  = k0 + kk;
            float makk = (k < HH) ? __ldg(&ma[k]) : 0.f;
            #pragma unroll
            for (int q = 0; q < 4; q++) {
                int j = (tid >> 4) + q * 16;
                float v = 0.f;
                if (k < HH)
                    v = adjT[j] * makk - prev[((g * 64 + j) * 64 + i) * HH + k];
                As[kk][j] = v;
            }
        }
        {
            int nn = tid & 63;
            int c  = col0 + nn;
            #pragma unroll
            for (int q = 0; q < 4; q++) {
                int kk = (tid >> 6) + q * 4;
                int k  = k0 + kk;
                Bs[kk][nn] = (k < HH && c < HH) ? W[k * HH + c] : 0.f;
            }
        }
        __syncthreads();
        #pragma unroll
        for (int kk = 0; kk < 16; kk++) {
            float4 a4 = *(const float4*)&As[kk][ty * 4];
            float4 b4 = *(const float4*)&Bs[kk][tx * 4];
            float a[4] = {a4.x, a4.y, a4.z, a4.w};
            float b[4] = {b4.x, b4.y, b4.z, b4.w};
            #pragma unroll
            for (int ii = 0; ii < 4; ii++)
                #pragma unroll
                for (int jj = 0; jj < 4; jj++)
                    acc[ii][jj] += a[ii] * b[jj];
        }
    }
    #pragma unroll
    for (int ii = 0; ii < 4; ii++) {
        int j = ty * 4 + ii;             // output j
        int rowout = (g * 64 + i) * 64 + j;
        float sv = smv[j];
        #pragma unroll
        for (int jj = 0; jj < 4; jj++) {
            int c = col0 + tx * 4 + jj;
            if (c < HH) {
                float v = g_input_bond[rowout * HH + c] + acc[ii][jj];
                v = v > 0.f ? v : 0.f;
                out[rowout * HH + c] = v * sv;
            }
        }
    }
}

// ---------------------------------------------------------------------------
// Output GEMM: atom_hiddens = relu([agg, msg_atom, input_atom] @ W_o + b_o)
// A: [2048, 900] (virtual concat), W_o: [900, 300]
// ---------------------------------------------------------------------------
__global__ void k_output(const float* __restrict__ W, const float* __restrict__ bias,
                         float* __restrict__ out) {
    const int row0 = blockIdx.y * 64;
    const int col0 = blockIdx.x * 64;
    __shared__ float As[16][68];
    __shared__ float Bs[16][68];
    const int tid = threadIdx.x;
    const int tx = tid & 15, ty = tid >> 4;
    float acc[4][4] = {};
    for (int k0 = 0; k0 < 900; k0 += 16) {
        __syncthreads();
        {
            int kk = tid & 15;
            int k  = k0 + kk;
            #pragma unroll
            for (int q = 0; q < 4; q++) {
                int r = (tid >> 4) + q * 16;
                int row = row0 + r;
                float v = 0.f;
                if (k < 900) {
                    if (k < 300)       v = g_agg[row * HH + k];
                    else if (k < 600)  v = g_msg_atom[row * HH + (k - 300)];
                    else               v = g_input_atom[row * HH + (k - 600)];
                }
                As[kk][r] = v;
            }
        }
        {
            int nn = tid & 63;
            int c  = col0 + nn;
            #pragma unroll
            for (int q = 0; q < 4; q++) {
                int kk = (tid >> 6) + q * 4;
                int k  = k0 + kk;
                Bs[kk][nn] = (k < 900 && c < HH) ? W[k * HH + c] : 0.f;
            }
        }
        __syncthreads();
        #pragma unroll
        for (int kk = 0; kk < 16; kk++) {
            float4 a4 = *(const float4*)&As[kk][ty * 4];
            float4 b4 = *(const float4*)&Bs[kk][tx * 4];
            float a[4] = {a4.x, a4.y, a4.z, a4.w};
            float b[4] = {b4.x, b4.y, b4.z, b4.w};
            #pragma unroll
            for (int i = 0; i < 4; i++)
                #pragma unroll
                for (int j = 0; j < 4; j++)
                    acc[i][j] += a[i] * b[j];
        }
    }
    #pragma unroll
    for (int i = 0; i < 4; i++) {
        int r = row0 + ty * 4 + i;
        #pragma unroll
        for (int j = 0; j < 4; j++) {
            int c = col0 + tx * 4 + j;
            if (c < HH) {
                float v = acc[i][j] + bias[c];
                out[r * HH + c] = v > 0.f ? v : 0.f;
            }
        }
    }
}

// ---------------------------------------------------------------------------
extern "C" void kernel_launch(void* const* d_in, const int* in_sizes, int n_in,
                              void* d_out, int out_size) {
    const float* f_atoms  = (const float*)d_in[0];
    const float* f_bonds  = (const float*)d_in[1];
    const float* adj      = (const float*)d_in[2];
    const float* W_i_atom = (const float*)d_in[3];
    const float* W_i_bond = (const float*)d_in[4];
    const float* W_h0     = (const float*)d_in[5];
    const float* W_h1     = (const float*)d_in[6];
    const float* W_o      = (const float*)d_in[7];
    const float* b_o      = (const float*)d_in[8];
    float* out = (float*)d_out;

    float *p_inbond = 0, *p_mbA = 0, *p_mbB = 0;
    cudaGetSymbolAddress((void**)&p_inbond, g_input_bond);
    cudaGetSymbolAddress((void**)&p_mbA, g_mbA);
    cudaGetSymbolAddress((void**)&p_mbB, g_mbB);

    // Output layout: [atom_hiddens (2048*300) | message_bond (131072*300)].
    // If the harness only materializes the first output, fall back to scratch.
    float* mb_final = (out_size >= AR * HH + BR * HH) ? (out + AR * HH) : p_mbB;

    dim3 blk(256);
    k_input_atom<<<dim3(5, 32), blk>>>(f_atoms, W_i_atom);
    k_input_bond<<<dim3(5, 2048), blk>>>(f_bonds, adj, W_i_bond);

    // depth step 0 (message_bond == input_bond initially; no copy needed)
    k_agg<<<2048, 320>>>(p_inbond, 1);
    k_resonance<<<2048, 64>>>(adj);
    k_bond_update<<<dim3(5, 2048), blk>>>(adj, W_h0, p_inbond, p_mbA);

    // depth step 1 — final message_bond written straight into d_out region
    k_agg<<<2048, 320>>>(p_mbA, 1);
    k_resonance<<<2048, 64>>>(adj);
    k_bond_update<<<dim3(5, 2048), blk>>>(adj, W_h1, p_mbA, mb_final);

    // readout
    k_agg<<<2048, 320>>>(mb_final, 0);
    k_output<<<dim3(5, 32), blk>>>(W_o, b_o, out);
}